// round 13
// baseline (speedup 1.0000x reference)
#include <cuda_runtime.h>
#include <cuda_bf16.h>
#include <stdint.h>
#include <math.h>

#define BB 16
#define LBL 48
#define PRED 336
#define LSEQ 384
#define CIN 7
#define TFD 4
#define DM 512
#define DIN 1024
#define NST 16
#define DTR 32
#define DCONV 4
#define NLAYER 2
#define EPSF 1e-5f

#define NTOK (BB*LSEQ)   // 6144 rows
#define KEMB 28

typedef __nv_bfloat16 bf16;

// ------------------- scratch (static device globals; no allocs) -------------
__device__ float g_x  [NTOK*DM];
__device__ bf16  g_xnh[NTOK*DM];
__device__ float g_xin[NTOK*DIN];
__device__ bf16  g_zh [NTOK*DIN];
__device__ bf16  g_xch[NTOK*DIN];
__device__ float g_dbc[NTOK*64];
__device__ bf16  g_yh [NTOK*DIN];
__device__ float g_mean[BB*CIN];
__device__ float g_std [BB*CIN];
__device__ bf16  g_wih[NLAYER*2*DIN*DM];
__device__ bf16  g_woh[NLAYER*DM*DIN];
__device__ float g_a28[NTOK*KEMB];
__device__ float g_w28[DM*KEMB];

// ------------------------------- helpers ------------------------------------
__device__ __forceinline__ float block_reduce_sum(float v, float* red) {
    __syncthreads();
    int lane = threadIdx.x & 31, wid = threadIdx.x >> 5;
    #pragma unroll
    for (int o = 16; o; o >>= 1) v += __shfl_xor_sync(0xffffffffu, v, o);
    if (lane == 0) red[wid] = v;
    __syncthreads();
    if (wid == 0) {
        float t = (lane < (int)(blockDim.x >> 5)) ? red[lane] : 0.f;
        #pragma unroll
        for (int o = 16; o; o >>= 1) t += __shfl_xor_sync(0xffffffffu, t, o);
        if (lane == 0) red[0] = t;
    }
    __syncthreads();
    return red[0];
}

__device__ __forceinline__ float silu_fast(float x) {
    return __fdividef(x, 1.f + __expf(-x));
}

#define CP_ASYNC16(dst, src) \
    asm volatile("cp.async.cg.shared.global [%0], [%1], 16;" :: "r"(dst), "l"(src))

// --------------------- weight bf16 pre-conversion ---------------------------
__global__ void cvtwh_kernel(const float* __restrict__ src, bf16* __restrict__ dst, int n) {
    int i = blockIdx.x * 256 + threadIdx.x;
    if (i < n) dst[i] = __float2bfloat16(src[i]);
}

// --------------------- mean/std over label window (warp per (b,c)) ----------
__global__ void meanstd_kernel(const float* __restrict__ x_dec,
                               float* __restrict__ mean, float* __restrict__ stdv) {
    int b = blockIdx.x / CIN, c = blockIdx.x % CIN;
    int lane = threadIdx.x;
    float s = 0.f;
    for (int t = lane; t < LBL; t += 32) s += x_dec[(b*LSEQ + t)*CIN + c];
    #pragma unroll
    for (int o = 16; o; o >>= 1) s += __shfl_xor_sync(0xffffffffu, s, o);
    float m = s / (float)LBL;
    float v = 0.f;
    for (int t = lane; t < LBL; t += 32) {
        float d = x_dec[(b*LSEQ + t)*CIN + c] - m;
        v += d*d;
    }
    #pragma unroll
    for (int o = 16; o; o >>= 1) v += __shfl_xor_sync(0xffffffffu, v, o);
    if (lane == 0) {
        mean[blockIdx.x] = m;
        stdv[blockIdx.x] = sqrtf(v / (float)LBL + EPSF);
    }
}

// ---------------- embed prep: window matrix + packed weights -----------------
__global__ void embed_prep(const float* __restrict__ x_dec,
                           const float* __restrict__ mark,
                           const float* __restrict__ mean,
                           const float* __restrict__ stdv,
                           float* __restrict__ A28) {
    int i = blockIdx.x * 256 + threadIdx.x;
    if (i >= NTOK*KEMB) return;
    int col = i % KEMB, tok = i / KEMB;
    int b = tok / LSEQ, t = tok % LSEQ;
    float v = 0.f;
    if (col < 21) {
        int c = col / 3, k = col % 3;
        int s = (t - 1 + k + LSEQ) % LSEQ;
        v = x_dec[(b*LSEQ + s)*CIN + c];
        if (s < LBL) v = (v - mean[b*CIN + c]) / stdv[b*CIN + c];
    } else if (col < 25) {
        v = mark[(b*LSEQ + t)*TFD + col - 21];
    }
    A28[i] = v;
}

__global__ void w28_prep(const float* __restrict__ token_w,
                         const float* __restrict__ timef_w,
                         float* __restrict__ W28) {
    int i = blockIdx.x * 256 + threadIdx.x;
    if (i >= DM*KEMB) return;
    int m = i / KEMB, j = i % KEMB;
    float v = 0.f;
    if (j < 21)      v = token_w[m*21 + j];
    else if (j < 25) v = timef_w[m*TFD + j - 21];
    W28[i] = v;
}

// --------------------------- layernorm (rows of DM) -------------------------
__global__ void lnh_kernel(const float* __restrict__ x,
                           const float* __restrict__ w,
                           const float* __restrict__ bb,
                           bf16* __restrict__ out) {
    __shared__ float red[32];
    int row = blockIdx.x;
    const float* xr = x + (size_t)row*DM;
    int tid = threadIdx.x;
    float v0 = xr[tid], v1 = xr[tid + 256];
    float s = block_reduce_sum(v0 + v1, red);
    float m = s * (1.f/(float)DM);
    float d0 = v0 - m, d1 = v1 - m;
    float vs = block_reduce_sum(d0*d0 + d1*d1, red);
    float inv = rsqrtf(vs * (1.f/(float)DM) + EPSF);
    out[(size_t)row*DM + tid]       = __float2bfloat16(d0*inv*w[tid]       + bb[tid]);
    out[(size_t)row*DM + tid + 256] = __float2bfloat16(d1*inv*w[tid + 256] + bb[tid + 256]);
}

// ---------------------- BF16 tensor-core GEMM, cp.async 3-stage --------------
// MODE 2: C(f32) += result (residual).
// MODE 4: split output — col < DIN -> fp32 C (ldc=DIN); col >= DIN -> bf16 Ch.
#define SROWH 40
#define TILEH (128*SROWH)   // halves
template<int MODE>
__global__ void __launch_bounds__(256, 2) gemm_bf(const bf16* __restrict__ A, int lda,
                                                  const bf16* __restrict__ W,
                                                  float* __restrict__ C, int ldc,
                                                  bf16* __restrict__ Ch,
                                                  int K) {
    extern __shared__ bf16 smh[];
    const int tid = threadIdx.x;
    const int lane = tid & 31, warp = tid >> 5;
    const int wm = warp >> 1, wn = warp & 1;
    const int row0 = blockIdx.y * 128, col0 = blockIdx.x * 128;
    const int KT = K >> 5;
    const unsigned sbase = (unsigned)__cvta_generic_to_shared(smh);

    float acc[2][8][4];
    #pragma unroll
    for (int i = 0; i < 2; i++)
        #pragma unroll
        for (int j = 0; j < 8; j++)
            #pragma unroll
            for (int q = 0; q < 4; q++) acc[i][j][q] = 0.f;

    #define ISSUE(kt_, s_) do {                                                 \
        int k0_ = (kt_) << 5;                                                   \
        _Pragma("unroll")                                                       \
        for (int h_ = 0; h_ < 2; h_++) {                                        \
            int c_ = tid + h_*256;                                              \
            int r_ = c_ >> 2, q_ = (c_ & 3) * 8;                                \
            const bf16* ga_ = A + (size_t)(row0 + r_)*lda + k0_ + q_;           \
            const bf16* gb_ = W + (size_t)(col0 + r_)*K   + k0_ + q_;           \
            unsigned da_ = sbase + (unsigned)(((s_)*2*TILEH + r_*SROWH + q_)*2);\
            unsigned db_ = sbase + (unsigned)(((s_)*2*TILEH + TILEH + r_*SROWH + q_)*2); \
            CP_ASYNC16(da_, ga_);                                               \
            CP_ASYNC16(db_, gb_);                                               \
        }                                                                       \
        asm volatile("cp.async.commit_group;");                                 \
    } while (0)

    ISSUE(0, 0);
    ISSUE(1, 1);

    for (int kt = 0; kt < KT; kt++) {
        if (kt + 2 < KT) asm volatile("cp.async.wait_group 1;");
        else             asm volatile("cp.async.wait_group 0;");
        __syncthreads();
        if (kt + 2 < KT) ISSUE(kt + 2, (kt + 2) % 3);

        const bf16* As_ = smh + (kt % 3) * 2 * TILEH;
        const bf16* Bs_ = As_ + TILEH;

        #pragma unroll
        for (int kk = 0; kk < 2; kk++) {
            const int kf2 = kk*16 + (lane & 3)*2;
            unsigned a0[2], a1[2], a2[2], a3[2];
            #pragma unroll
            for (int i = 0; i < 2; i++) {
                int r = wm*32 + i*16 + (lane >> 2);
                a0[i] = *(const unsigned*)(As_ + r*SROWH + kf2);
                a1[i] = *(const unsigned*)(As_ + (r+8)*SROWH + kf2);
                a2[i] = *(const unsigned*)(As_ + r*SROWH + kf2 + 8);
                a3[i] = *(const unsigned*)(As_ + (r+8)*SROWH + kf2 + 8);
            }
            #pragma unroll
            for (int j = 0; j < 8; j++) {
                int n = wn*64 + j*8 + (lane >> 2);
                unsigned b0 = *(const unsigned*)(Bs_ + n*SROWH + kf2);
                unsigned b1 = *(const unsigned*)(Bs_ + n*SROWH + kf2 + 8);
                #pragma unroll
                for (int i = 0; i < 2; i++) {
                    asm volatile(
                        "mma.sync.aligned.m16n8k16.row.col.f32.bf16.bf16.f32 "
                        "{%0,%1,%2,%3}, {%4,%5,%6,%7}, {%8,%9}, {%0,%1,%2,%3};"
                        : "+f"(acc[i][j][0]), "+f"(acc[i][j][1]),
                          "+f"(acc[i][j][2]), "+f"(acc[i][j][3])
                        : "r"(a0[i]), "r"(a1[i]), "r"(a2[i]), "r"(a3[i]),
                          "r"(b0), "r"(b1));
                }
            }
        }
    }
    #undef ISSUE

    #pragma unroll
    for (int i = 0; i < 2; i++) {
        int gr = row0 + wm*32 + i*16 + (lane >> 2);
        #pragma unroll
        for (int j = 0; j < 8; j++) {
            int gc = col0 + wn*64 + j*8 + (lane & 3)*2;
            if (MODE == 2) {
                float* p0 = C + (size_t)gr*ldc + gc;
                float* p1 = C + (size_t)(gr + 8)*ldc + gc;
                p0[0] += acc[i][j][0]; p0[1] += acc[i][j][1];
                p1[0] += acc[i][j][2]; p1[1] += acc[i][j][3];
            } else { // MODE 4 split
                if (col0 < DIN) {
                    float* p0 = C + (size_t)gr*DIN + gc;
                    float* p1 = C + (size_t)(gr + 8)*DIN + gc;
                    p0[0] = acc[i][j][0]; p0[1] = acc[i][j][1];
                    p1[0] = acc[i][j][2]; p1[1] = acc[i][j][3];
                } else {
                    int zc = gc - DIN;
                    bf16* q0 = Ch + (size_t)gr*DIN + zc;
                    bf16* q1 = Ch + (size_t)(gr + 8)*DIN + zc;
                    q0[0] = __float2bfloat16(acc[i][j][0]);
                    q0[1] = __float2bfloat16(acc[i][j][1]);
                    q1[0] = __float2bfloat16(acc[i][j][2]);
                    q1[1] = __float2bfloat16(acc[i][j][3]);
                }
            }
        }
    }
}

// ------------------------------ SIMT GEMM ------------------------------------
template<typename TA, int BM, int BN, int BK, int TM, int TN>
__global__ void gemm_kernel(const TA* __restrict__ A, int lda,
                            const float* __restrict__ W,
                            float* __restrict__ C, int ldc,
                            int M, int Nn, int K) {
    constexpr int THREADS = (BM/TM)*(BN/TN);
    __shared__ float As[BK][BM];
    __shared__ float Bs[BK][BN];
    int tid = threadIdx.x;
    int tx = tid % (BN/TN);
    int ty = tid / (BN/TN);
    int row0 = blockIdx.y * BM;
    int col0 = blockIdx.x * BN;
    float acc[TM][TN];
    #pragma unroll
    for (int i = 0; i < TM; i++)
        #pragma unroll
        for (int j = 0; j < TN; j++) acc[i][j] = 0.f;

    for (int k0 = 0; k0 < K; k0 += BK) {
        #pragma unroll
        for (int i = tid; i < BM*BK; i += THREADS) {
            int m = i / BK, kk = i % BK;
            As[kk][m] = (float)A[(size_t)(row0 + m)*lda + k0 + kk];
        }
        #pragma unroll
        for (int i = tid; i < BN*BK; i += THREADS) {
            int n = i / BK, kk = i % BK;
            Bs[kk][n] = W[(size_t)(col0 + n)*K + k0 + kk];
        }
        __syncthreads();
        #pragma unroll
        for (int kk = 0; kk < BK; kk++) {
            float a[TM], bfr[TN];
            #pragma unroll
            for (int i = 0; i < TM; i++) a[i] = As[kk][ty*TM + i];
            #pragma unroll
            for (int j = 0; j < TN; j++) bfr[j] = Bs[kk][tx*TN + j];
            #pragma unroll
            for (int i = 0; i < TM; i++)
                #pragma unroll
                for (int j = 0; j < TN; j++) acc[i][j] += a[i]*bfr[j];
        }
        __syncthreads();
    }
    #pragma unroll
    for (int i = 0; i < TM; i++) {
        int gm = row0 + ty*TM + i;
        #pragma unroll
        for (int j = 0; j < TN; j++) {
            int gn = col0 + tx*TN + j;
            C[(size_t)gm*ldc + gn] = acc[i][j];
        }
    }
}

// -------------- depthwise causal conv (k=4) + SiLU, float4 -> bf16 ----------
__global__ void dwconv_kernel(const float* __restrict__ xin,   // (B,L,DIN)
                              const float* __restrict__ w,
                              const float* __restrict__ bias,
                              bf16* __restrict__ xch) {
    int gid = blockIdx.x * blockDim.x + threadIdx.x;   // over NTOK*DIN/4
    int d4 = gid % (DIN/4);
    int t  = (gid / (DIN/4)) % LSEQ;
    int b  = gid / ((DIN/4) * LSEQ);
    const float* xp = xin + (size_t)b * LSEQ * DIN + d4*4;
    float4 w0 = ((const float4*)w)[d4*4 + 0];
    float4 w1 = ((const float4*)w)[d4*4 + 1];
    float4 w2 = ((const float4*)w)[d4*4 + 2];
    float4 w3 = ((const float4*)w)[d4*4 + 3];
    float4 acc = ((const float4*)bias)[d4];
    #pragma unroll
    for (int k = 0; k < DCONV; k++) {
        int s = t - (DCONV-1) + k;
        if (s >= 0) {
            float4 xv = *(const float4*)(xp + (size_t)s*DIN);
            float wk0 = (&w0.x)[k], wk1 = (&w1.x)[k], wk2 = (&w2.x)[k], wk3 = (&w3.x)[k];
            acc.x += xv.x*wk0; acc.y += xv.y*wk1; acc.z += xv.z*wk2; acc.w += xv.w*wk3;
        }
    }
    __nv_bfloat162 lo = __floats2bfloat162_rn(silu_fast(acc.x), silu_fast(acc.y));
    __nv_bfloat162 hi = __floats2bfloat162_rn(silu_fast(acc.z), silu_fast(acc.w));
    ((__nv_bfloat162*)xch)[gid*2]     = lo;
    ((__nv_bfloat162*)xch)[gid*2 + 1] = hi;
}

// --------------- fused dt_proj + softplus + selective scan ------------------
// thread = (b, d); dbc(f32) + u/z(bf16) chunks double-buffered via cp.async.
#define CH 32
#define NCH (LSEQ/CH)
#define BUFB (CH*64*4 + 2*CH*128*2)   // 24576 bytes per buffer
#define SCAN_SMEM (2*BUFB)            // 49152
__global__ void __launch_bounds__(128) dtscan_kernel(
    const bf16* __restrict__ xch,
    const bf16* __restrict__ zh,
    const float* __restrict__ dbc,
    const float* __restrict__ dtw,   // (DIN, DTR)
    const float* __restrict__ dtb,   // (DIN)
    const float* __restrict__ A_log, // (DIN, NST)
    const float* __restrict__ Dp,    // (DIN)
    bf16* __restrict__ y) {
    extern __shared__ char smc[];
    const unsigned sbase = (unsigned)__cvta_generic_to_shared(smc);
    int b = blockIdx.x;
    int d0 = blockIdx.y * 128;
    int d = d0 + threadIdx.x;
    float h[NST], a[NST], w[DTR];
    #pragma unroll
    for (int n = 0; n < NST; n++) {
        h[n] = 0.f;
        a[n] = -__expf(A_log[d*NST + n]);
    }
    #pragma unroll
    for (int j = 0; j < DTR; j++) w[j] = dtw[d*DTR + j];
    float bias = dtb[d], Dd = Dp[d];
    bool geom = true;
    #pragma unroll
    for (int n = 1; n < NST; n++) {
        float pred = (float)(n+1) * a[0];
        if (fabsf(a[n] - pred) > 1e-4f * fmaxf(1.f, fabsf(a[n]))) geom = false;
    }
    const float* dbc_b = dbc + (size_t)b * LSEQ * 64;
    const bf16* u_b = xch + (size_t)b * LSEQ * DIN + d0;
    const bf16* z_b = zh  + (size_t)b * LSEQ * DIN + d0;
    size_t ybase = (size_t)b * LSEQ * DIN + d;

    #define PRE(c_, bu_) do {                                                   \
        int t0_ = (c_)*CH;                                                      \
        for (int i_ = threadIdx.x; i_ < CH*16; i_ += 128) {                     \
            int tt_ = i_ >> 4, q_ = i_ & 15;                                    \
            CP_ASYNC16(sbase + (unsigned)((bu_)*BUFB + tt_*256 + q_*16),        \
                       dbc_b + (size_t)(t0_+tt_)*64 + q_*4);                    \
            CP_ASYNC16(sbase + (unsigned)((bu_)*BUFB + CH*256 + tt_*256 + q_*16),\
                       u_b + (size_t)(t0_+tt_)*DIN + q_*8);                     \
            CP_ASYNC16(sbase + (unsigned)((bu_)*BUFB + 2*CH*256 + tt_*256 + q_*16),\
                       z_b + (size_t)(t0_+tt_)*DIN + q_*8);                     \
        }                                                                       \
        asm volatile("cp.async.commit_group;");                                 \
    } while (0)

    PRE(0, 0);
    int bu = 0;
    for (int c = 0; c < NCH; c++) {
        asm volatile("cp.async.wait_group 0;");
        __syncthreads();
        if (c + 1 < NCH) PRE(c + 1, bu ^ 1);
        const float* dchunk = (const float*)(smc + bu*BUFB);
        const bf16*  uchunk = (const bf16*)(smc + bu*BUFB + CH*256);
        const bf16*  zchunk = (const bf16*)(smc + bu*BUFB + 2*CH*256);
        for (int tt = 0; tt < CH; tt++) {
            float u  = __bfloat162float(uchunk[tt*128 + threadIdx.x]);
            float zv = __bfloat162float(zchunk[tt*128 + threadIdx.x]);
            const float4* dr = (const float4*)(dchunk + tt*64);
            // dt_proj: 4 independent partial chains
            float v0 = bias, v1 = 0.f, v2 = 0.f, v3 = 0.f;
            #pragma unroll
            for (int j = 0; j < 2; j++) {
                float4 q0 = dr[4*j], q1 = dr[4*j+1], q2 = dr[4*j+2], q3 = dr[4*j+3];
                v0 += w[16*j+ 0]*q0.x + w[16*j+ 1]*q0.y + w[16*j+ 2]*q0.z + w[16*j+ 3]*q0.w;
                v1 += w[16*j+ 4]*q1.x + w[16*j+ 5]*q1.y + w[16*j+ 6]*q1.z + w[16*j+ 7]*q1.w;
                v2 += w[16*j+ 8]*q2.x + w[16*j+ 9]*q2.y + w[16*j+10]*q2.z + w[16*j+11]*q2.w;
                v3 += w[16*j+12]*q3.x + w[16*j+13]*q3.y + w[16*j+14]*q3.z + w[16*j+15]*q3.w;
            }
            float v = (v0 + v1) + (v2 + v3);
            float dt = (v > 20.f) ? v : __logf(1.f + __expf(v));
            float du = dt * u;
            const float4* Bv = (const float4*)(dchunk + tt*64 + DTR);
            const float4* Cv = (const float4*)(dchunk + tt*64 + DTR + NST);
            float dA[NST];
            if (geom) {
                float p1 = __expf(dt * a[0]);
                float p2 = p1*p1, p3 = p2*p1, p4 = p2*p2;
                float p5 = p4*p1, p6 = p4*p2, p7 = p4*p3, p8 = p4*p4;
                dA[0]=p1; dA[1]=p2; dA[2]=p3; dA[3]=p4;
                dA[4]=p5; dA[5]=p6; dA[6]=p7; dA[7]=p8;
                dA[8]=p8*p1; dA[9]=p8*p2; dA[10]=p8*p3; dA[11]=p8*p4;
                dA[12]=p8*p5; dA[13]=p8*p6; dA[14]=p8*p7; dA[15]=p8*p8;
            } else {
                #pragma unroll
                for (int n = 0; n < NST; n++) dA[n] = __expf(dt * a[n]);
            }
            float acc0 = 0.f, acc1 = 0.f;
            #pragma unroll
            for (int q = 0; q < 4; q++) {
                float4 Bq = Bv[q], Cq = Cv[q];
                h[4*q+0] = dA[4*q+0]*h[4*q+0] + du*Bq.x; acc0 += h[4*q+0]*Cq.x;
                h[4*q+1] = dA[4*q+1]*h[4*q+1] + du*Bq.y; acc1 += h[4*q+1]*Cq.y;
                h[4*q+2] = dA[4*q+2]*h[4*q+2] + du*Bq.z; acc0 += h[4*q+2]*Cq.z;
                h[4*q+3] = dA[4*q+3]*h[4*q+3] + du*Bq.w; acc1 += h[4*q+3]*Cq.w;
            }
            int t = c*CH + tt;
            y[ybase + (size_t)t*DIN] =
                __float2bfloat16(((acc0 + acc1) + u*Dd) * silu_fast(zv));
        }
        bu ^= 1;
    }
    #undef PRE
}

// --------------- output head: final LN + proj + denorm (fused) --------------
__global__ void outf_kernel(const float* __restrict__ x,
                            const float* __restrict__ fw,
                            const float* __restrict__ fb,
                            const float* __restrict__ out_w,
                            const float* __restrict__ mean,
                            const float* __restrict__ stdv,
                            float* __restrict__ out) {
    __shared__ float red[32];
    __shared__ float row[DM];
    int t_out = blockIdx.x, b = blockIdx.y;
    int r = b*LSEQ + LBL + t_out;
    int tid = threadIdx.x;             // 256
    const float* xr = x + (size_t)r*DM;
    float v0 = xr[tid], v1 = xr[tid + 256];
    float s = block_reduce_sum(v0 + v1, red);
    float m = s * (1.f/(float)DM);
    float d0 = v0 - m, d1 = v1 - m;
    float vs = block_reduce_sum(d0*d0 + d1*d1, red);
    float inv = rsqrtf(vs * (1.f/(float)DM) + EPSF);
    row[tid]       = d0*inv*fw[tid]       + fb[tid];
    row[tid + 256] = d1*inv*fw[tid + 256] + fb[tid + 256];
    __syncthreads();
    int c = tid >> 5, lane = tid & 31;
    if (c < CIN) {
        float acc = 0.f;
        #pragma unroll
        for (int i = 0; i < DM/32; i++) acc += row[lane + i*32] * out_w[c*DM + lane + i*32];
        #pragma unroll
        for (int o = 16; o; o >>= 1) acc += __shfl_xor_sync(0xffffffffu, acc, o);
        if (lane == 0)
            out[(size_t)(b*PRED + t_out)*CIN + c] = acc * stdv[b*CIN + c] + mean[b*CIN + c];
    }
}

// ------------------------------- launcher -----------------------------------
extern "C" void kernel_launch(void* const* d_in, const int* in_sizes, int n_in,
                              void* d_out, int out_size) {
    const float* x_dec    = (const float*)d_in[2];
    const float* mark     = (const float*)d_in[3];
    const float* token_w  = (const float*)d_in[4];
    const float* timef_w  = (const float*)d_in[5];
    const float* norm_w   = (const float*)d_in[6];
    const float* norm_b   = (const float*)d_in[7];
    const float* in_proj_w= (const float*)d_in[8];
    const float* conv_w   = (const float*)d_in[9];
    const float* conv_b   = (const float*)d_in[10];
    const float* xproj_w  = (const float*)d_in[11];
    const float* dtproj_w = (const float*)d_in[12];
    const float* dtproj_b = (const float*)d_in[13];
    const float* A_log    = (const float*)d_in[14];
    const float* Dp       = (const float*)d_in[15];
    const float* outproj_w= (const float*)d_in[16];
    const float* fin_w    = (const float*)d_in[17];
    const float* fin_b    = (const float*)d_in[18];
    const float* out_w    = (const float*)d_in[19];
    float* out = (float*)d_out;

    float *px, *pxin, *pdbc, *pmean, *pstd, *pa28, *pw28;
    bf16 *pxnh, *pzh, *pxch, *pyh, *pwih, *pwoh;
    cudaGetSymbolAddress((void**)&px,   g_x);
    cudaGetSymbolAddress((void**)&pxnh, g_xnh);
    cudaGetSymbolAddress((void**)&pxin, g_xin);
    cudaGetSymbolAddress((void**)&pzh,  g_zh);
    cudaGetSymbolAddress((void**)&pxch, g_xch);
    cudaGetSymbolAddress((void**)&pdbc, g_dbc);
    cudaGetSymbolAddress((void**)&pyh,  g_yh);
    cudaGetSymbolAddress((void**)&pmean,g_mean);
    cudaGetSymbolAddress((void**)&pstd, g_std);
    cudaGetSymbolAddress((void**)&pwih, g_wih);
    cudaGetSymbolAddress((void**)&pwoh, g_woh);
    cudaGetSymbolAddress((void**)&pa28, g_a28);
    cudaGetSymbolAddress((void**)&pw28, g_w28);

    const int SMEM_TC = 3*2*TILEH*2;   // 61440 bytes
    cudaFuncSetAttribute(gemm_bf<4>, cudaFuncAttributeMaxDynamicSharedMemorySize, SMEM_TC);
    cudaFuncSetAttribute(gemm_bf<2>, cudaFuncAttributeMaxDynamicSharedMemorySize, SMEM_TC);
    cudaFuncSetAttribute(dtscan_kernel, cudaFuncAttributeMaxDynamicSharedMemorySize, SCAN_SMEM);

    // one-time prep
    {
        int ni = NLAYER*2*DIN*DM, no = NLAYER*DM*DIN;
        cvtwh_kernel<<<(ni + 255)/256, 256>>>(in_proj_w, pwih, ni);
        cvtwh_kernel<<<(no + 255)/256, 256>>>(outproj_w, pwoh, no);
        w28_prep<<<(DM*KEMB + 255)/256, 256>>>(token_w, timef_w, pw28);
    }

    meanstd_kernel<<<BB*CIN, 32>>>(x_dec, pmean, pstd);
    embed_prep<<<(NTOK*KEMB + 255)/256, 256>>>(x_dec, mark, pmean, pstd, pa28);
    // embed GEMM: (6144x28) @ (512x28)^T -> (6144x512)
    gemm_kernel<float,64,64,28,4,4><<<dim3(DM/64, NTOK/64), 256>>>(
        pa28, KEMB, pw28, px, DM, NTOK, DM, KEMB);

    for (int l = 0; l < NLAYER; l++) {
        lnh_kernel<<<NTOK, 256>>>(px, norm_w + l*DM, norm_b + l*DM, pxnh);
        // in_proj: (6144x512) @ (2048x512)^T -> xin(f32) | zh(bf16)
        gemm_bf<4><<<dim3(2*DIN/128, NTOK/128), 256, SMEM_TC>>>(
            pxnh, DM, pwih + (size_t)l*2*DIN*DM, pxin, DIN, pzh, DM);
        dwconv_kernel<<<(NTOK*DIN/4)/256, 256>>>(pxin, conv_w + l*DIN*DCONV,
                                                 conv_b + l*DIN, pxch);
        // x_proj: (6144x1024)bf16 @ (64x1024)^T -> (6144x64)
        gemm_kernel<bf16,32,64,16,2,4><<<dim3(1, NTOK/32), 256>>>(
            pxch, DIN, xproj_w + (size_t)l*64*DIN, pdbc, 64, NTOK, 64, DIN);
        // fused dt_proj + softplus + selective scan + gate
        dtscan_kernel<<<dim3(BB, DIN/128), 128, SCAN_SMEM>>>(
            pxch, pzh, pdbc, dtproj_w + (size_t)l*DIN*DTR, dtproj_b + l*DIN,
            A_log + (size_t)l*DIN*NST, Dp + l*DIN, pyh);
        // out_proj (+residual): (6144x1024) @ (512x1024)^T -> += x
        gemm_bf<2><<<dim3(DM/128, NTOK/128), 256, SMEM_TC>>>(
            pyh, DIN, pwoh + (size_t)l*DM*DIN, px, DM, nullptr, DIN);
    }

    outf_kernel<<<dim3(PRED, BB), 256>>>(px, fin_w, fin_b, out_w, pmean, pstd, out);
}

// round 14
// speedup vs baseline: 1.2077x; 1.2077x over previous
#include <cuda_runtime.h>
#include <cuda_bf16.h>
#include <stdint.h>
#include <math.h>

#define BB 16
#define LBL 48
#define PRED 336
#define LSEQ 384
#define CIN 7
#define TFD 4
#define DM 512
#define DIN 1024
#define NST 16
#define DTR 32
#define DCONV 4
#define NLAYER 2
#define EPSF 1e-5f

#define NTOK (BB*LSEQ)   // 6144 rows
#define KEMB 28

typedef __nv_bfloat16 bf16;

// ------------------- scratch (static device globals; no allocs) -------------
__device__ float g_x  [NTOK*DM];
__device__ bf16  g_xnh[NTOK*DM];
__device__ float g_xz [NTOK*2*DIN];
__device__ float g_xc [NTOK*DIN];
__device__ float g_dbc[NTOK*64];
__device__ bf16  g_yh [NTOK*DIN];
__device__ float g_mean[BB*CIN];
__device__ float g_std [BB*CIN];
__device__ bf16  g_wih[NLAYER*2*DIN*DM];
__device__ bf16  g_woh[NLAYER*DM*DIN];
__device__ float g_a28[NTOK*KEMB];
__device__ float g_w28[DM*KEMB];

// ------------------------------- helpers ------------------------------------
__device__ __forceinline__ float block_reduce_sum(float v, float* red) {
    __syncthreads();
    int lane = threadIdx.x & 31, wid = threadIdx.x >> 5;
    #pragma unroll
    for (int o = 16; o; o >>= 1) v += __shfl_xor_sync(0xffffffffu, v, o);
    if (lane == 0) red[wid] = v;
    __syncthreads();
    if (wid == 0) {
        float t = (lane < (int)(blockDim.x >> 5)) ? red[lane] : 0.f;
        #pragma unroll
        for (int o = 16; o; o >>= 1) t += __shfl_xor_sync(0xffffffffu, t, o);
        if (lane == 0) red[0] = t;
    }
    __syncthreads();
    return red[0];
}

__device__ __forceinline__ float silu_fast(float x) {
    return __fdividef(x, 1.f + __expf(-x));
}

#define CP_ASYNC16(dst, src) \
    asm volatile("cp.async.cg.shared.global [%0], [%1], 16;" :: "r"(dst), "l"(src))

// --------------------- weight bf16 pre-conversion ---------------------------
__global__ void cvtwh_kernel(const float* __restrict__ src, bf16* __restrict__ dst, int n) {
    int i = blockIdx.x * 256 + threadIdx.x;
    if (i < n) dst[i] = __float2bfloat16(src[i]);
}

// --------------------- mean/std over label window (warp per (b,c)) ----------
__global__ void meanstd_kernel(const float* __restrict__ x_dec,
                               float* __restrict__ mean, float* __restrict__ stdv) {
    int b = blockIdx.x / CIN, c = blockIdx.x % CIN;
    int lane = threadIdx.x;
    float s = 0.f;
    for (int t = lane; t < LBL; t += 32) s += x_dec[(b*LSEQ + t)*CIN + c];
    #pragma unroll
    for (int o = 16; o; o >>= 1) s += __shfl_xor_sync(0xffffffffu, s, o);
    float m = s / (float)LBL;
    float v = 0.f;
    for (int t = lane; t < LBL; t += 32) {
        float d = x_dec[(b*LSEQ + t)*CIN + c] - m;
        v += d*d;
    }
    #pragma unroll
    for (int o = 16; o; o >>= 1) v += __shfl_xor_sync(0xffffffffu, v, o);
    if (lane == 0) {
        mean[blockIdx.x] = m;
        stdv[blockIdx.x] = sqrtf(v / (float)LBL + EPSF);
    }
}

// ---------------- embed prep: window matrix + packed weights -----------------
__global__ void embed_prep(const float* __restrict__ x_dec,
                           const float* __restrict__ mark,
                           const float* __restrict__ mean,
                           const float* __restrict__ stdv,
                           float* __restrict__ A28) {
    int i = blockIdx.x * 256 + threadIdx.x;
    if (i >= NTOK*KEMB) return;
    int col = i % KEMB, tok = i / KEMB;
    int b = tok / LSEQ, t = tok % LSEQ;
    float v = 0.f;
    if (col < 21) {
        int c = col / 3, k = col % 3;
        int s = (t - 1 + k + LSEQ) % LSEQ;
        v = x_dec[(b*LSEQ + s)*CIN + c];
        if (s < LBL) v = (v - mean[b*CIN + c]) / stdv[b*CIN + c];
    } else if (col < 25) {
        v = mark[(b*LSEQ + t)*TFD + col - 21];
    }
    A28[i] = v;
}

__global__ void w28_prep(const float* __restrict__ token_w,
                         const float* __restrict__ timef_w,
                         float* __restrict__ W28) {
    int i = blockIdx.x * 256 + threadIdx.x;
    if (i >= DM*KEMB) return;
    int m = i / KEMB, j = i % KEMB;
    float v = 0.f;
    if (j < 21)      v = token_w[m*21 + j];
    else if (j < 25) v = timef_w[m*TFD + j - 21];
    W28[i] = v;
}

// -------------------- layernorm (warp per row of DM) -> bf16 ----------------
__global__ void lnh_kernel(const float* __restrict__ x,
                           const float* __restrict__ w,
                           const float* __restrict__ bb,
                           bf16* __restrict__ out) {
    int warp = threadIdx.x >> 5, lane = threadIdx.x & 31;
    int row = blockIdx.x * 8 + warp;
    const float4* xr = (const float4*)(x + (size_t)row*DM);
    float4 v[4];
    float s = 0.f;
    #pragma unroll
    for (int i = 0; i < 4; i++) {
        v[i] = xr[lane + i*32];
        s += (v[i].x + v[i].y) + (v[i].z + v[i].w);
    }
    #pragma unroll
    for (int o = 16; o; o >>= 1) s += __shfl_xor_sync(0xffffffffu, s, o);
    float m = s * (1.f/(float)DM);
    float vs = 0.f;
    #pragma unroll
    for (int i = 0; i < 4; i++) {
        v[i].x -= m; v[i].y -= m; v[i].z -= m; v[i].w -= m;
        vs += (v[i].x*v[i].x + v[i].y*v[i].y) + (v[i].z*v[i].z + v[i].w*v[i].w);
    }
    #pragma unroll
    for (int o = 16; o; o >>= 1) vs += __shfl_xor_sync(0xffffffffu, vs, o);
    float inv = rsqrtf(vs * (1.f/(float)DM) + EPSF);
    __nv_bfloat162* orow = (__nv_bfloat162*)(out + (size_t)row*DM);
    #pragma unroll
    for (int i = 0; i < 4; i++) {
        float4 wv = ((const float4*)w)[lane + i*32];
        float4 bv = ((const float4*)bb)[lane + i*32];
        float o0 = v[i].x*inv*wv.x + bv.x;
        float o1 = v[i].y*inv*wv.y + bv.y;
        float o2 = v[i].z*inv*wv.z + bv.z;
        float o3 = v[i].w*inv*wv.w + bv.w;
        orow[(lane + i*32)*2]     = __floats2bfloat162_rn(o0, o1);
        orow[(lane + i*32)*2 + 1] = __floats2bfloat162_rn(o2, o3);
    }
}

// ---------------------- BF16 tensor-core GEMM, cp.async 3-stage --------------
#define SROWH 40
#define TILEH (128*SROWH)   // halves
template<int MODE>
__global__ void __launch_bounds__(256, 2) gemm_bf(const bf16* __restrict__ A, int lda,
                                                  const bf16* __restrict__ W,
                                                  float* __restrict__ C, int ldc,
                                                  int K) {
    extern __shared__ bf16 smh[];
    const int tid = threadIdx.x;
    const int lane = tid & 31, warp = tid >> 5;
    const int wm = warp >> 1, wn = warp & 1;
    const int row0 = blockIdx.y * 128, col0 = blockIdx.x * 128;
    const int KT = K >> 5;
    const unsigned sbase = (unsigned)__cvta_generic_to_shared(smh);

    float acc[2][8][4];
    #pragma unroll
    for (int i = 0; i < 2; i++)
        #pragma unroll
        for (int j = 0; j < 8; j++)
            #pragma unroll
            for (int q = 0; q < 4; q++) acc[i][j][q] = 0.f;

    #define ISSUE(kt_, s_) do {                                                 \
        int k0_ = (kt_) << 5;                                                   \
        _Pragma("unroll")                                                       \
        for (int h_ = 0; h_ < 2; h_++) {                                        \
            int c_ = tid + h_*256;                                              \
            int r_ = c_ >> 2, q_ = (c_ & 3) * 8;                                \
            const bf16* ga_ = A + (size_t)(row0 + r_)*lda + k0_ + q_;           \
            const bf16* gb_ = W + (size_t)(col0 + r_)*K   + k0_ + q_;           \
            unsigned da_ = sbase + (unsigned)(((s_)*2*TILEH + r_*SROWH + q_)*2);\
            unsigned db_ = sbase + (unsigned)(((s_)*2*TILEH + TILEH + r_*SROWH + q_)*2); \
            CP_ASYNC16(da_, ga_);                                               \
            CP_ASYNC16(db_, gb_);                                               \
        }                                                                       \
        asm volatile("cp.async.commit_group;");                                 \
    } while (0)

    ISSUE(0, 0);
    ISSUE(1, 1);

    for (int kt = 0; kt < KT; kt++) {
        if (kt + 2 < KT) asm volatile("cp.async.wait_group 1;");
        else             asm volatile("cp.async.wait_group 0;");
        __syncthreads();
        if (kt + 2 < KT) ISSUE(kt + 2, (kt + 2) % 3);

        const bf16* As_ = smh + (kt % 3) * 2 * TILEH;
        const bf16* Bs_ = As_ + TILEH;

        #pragma unroll
        for (int kk = 0; kk < 2; kk++) {
            const int kf2 = kk*16 + (lane & 3)*2;
            unsigned a0[2], a1[2], a2[2], a3[2];
            #pragma unroll
            for (int i = 0; i < 2; i++) {
                int r = wm*32 + i*16 + (lane >> 2);
                a0[i] = *(const unsigned*)(As_ + r*SROWH + kf2);
                a1[i] = *(const unsigned*)(As_ + (r+8)*SROWH + kf2);
                a2[i] = *(const unsigned*)(As_ + r*SROWH + kf2 + 8);
                a3[i] = *(const unsigned*)(As_ + (r+8)*SROWH + kf2 + 8);
            }
            #pragma unroll
            for (int j = 0; j < 8; j++) {
                int n = wn*64 + j*8 + (lane >> 2);
                unsigned b0 = *(const unsigned*)(Bs_ + n*SROWH + kf2);
                unsigned b1 = *(const unsigned*)(Bs_ + n*SROWH + kf2 + 8);
                #pragma unroll
                for (int i = 0; i < 2; i++) {
                    asm volatile(
                        "mma.sync.aligned.m16n8k16.row.col.f32.bf16.bf16.f32 "
                        "{%0,%1,%2,%3}, {%4,%5,%6,%7}, {%8,%9}, {%0,%1,%2,%3};"
                        : "+f"(acc[i][j][0]), "+f"(acc[i][j][1]),
                          "+f"(acc[i][j][2]), "+f"(acc[i][j][3])
                        : "r"(a0[i]), "r"(a1[i]), "r"(a2[i]), "r"(a3[i]),
                          "r"(b0), "r"(b1));
                }
            }
        }
    }
    #undef ISSUE

    #pragma unroll
    for (int i = 0; i < 2; i++) {
        int gr = row0 + wm*32 + i*16 + (lane >> 2);
        #pragma unroll
        for (int j = 0; j < 8; j++) {
            int gc = col0 + wn*64 + j*8 + (lane & 3)*2;
            float* p0 = C + (size_t)gr*ldc + gc;
            float* p1 = C + (size_t)(gr + 8)*ldc + gc;
            if (MODE == 2) {
                p0[0] += acc[i][j][0]; p0[1] += acc[i][j][1];
                p1[0] += acc[i][j][2]; p1[1] += acc[i][j][3];
            } else {
                p0[0] = acc[i][j][0]; p0[1] = acc[i][j][1];
                p1[0] = acc[i][j][2]; p1[1] = acc[i][j][3];
            }
        }
    }
}

// ------------------------------ SIMT GEMM ------------------------------------
// mode 0: store.  mode 3: atomicAdd (split-K).
template<int BM, int BN, int BK, int TM, int TN>
__global__ void gemm_kernel(const float* __restrict__ A, int lda,
                            const float* __restrict__ W,
                            const float* __restrict__ bias,
                            float* __restrict__ C, int ldc,
                            int M, int Nn, int K, int KC, int mode) {
    constexpr int THREADS = (BM/TM)*(BN/TN);
    __shared__ float As[BK][BM];
    __shared__ float Bs[BK][BN];
    int tid = threadIdx.x;
    int tx = tid % (BN/TN);
    int ty = tid / (BN/TN);
    int row0 = blockIdx.y * BM;
    int col0 = blockIdx.x * BN;
    int kbeg = blockIdx.z * KC;
    float acc[TM][TN];
    #pragma unroll
    for (int i = 0; i < TM; i++)
        #pragma unroll
        for (int j = 0; j < TN; j++) acc[i][j] = 0.f;

    for (int k0 = kbeg; k0 < kbeg + KC; k0 += BK) {
        #pragma unroll
        for (int i = tid; i < BM*BK; i += THREADS) {
            int m = i / BK, kk = i % BK;
            As[kk][m] = A[(size_t)(row0 + m)*lda + k0 + kk];
        }
        #pragma unroll
        for (int i = tid; i < BN*BK; i += THREADS) {
            int n = i / BK, kk = i % BK;
            Bs[kk][n] = W[(size_t)(col0 + n)*K + k0 + kk];
        }
        __syncthreads();
        #pragma unroll
        for (int kk = 0; kk < BK; kk++) {
            float a[TM], bfr[TN];
            #pragma unroll
            for (int i = 0; i < TM; i++) a[i] = As[kk][ty*TM + i];
            #pragma unroll
            for (int j = 0; j < TN; j++) bfr[j] = Bs[kk][tx*TN + j];
            #pragma unroll
            for (int i = 0; i < TM; i++)
                #pragma unroll
                for (int j = 0; j < TN; j++) acc[i][j] += a[i]*bfr[j];
        }
        __syncthreads();
    }
    #pragma unroll
    for (int i = 0; i < TM; i++) {
        int gm = row0 + ty*TM + i;
        #pragma unroll
        for (int j = 0; j < TN; j++) {
            int gn = col0 + tx*TN + j;
            float v = acc[i][j];
            if (mode == 3)      atomicAdd(&C[(size_t)gm*ldc + gn], v);
            else                C[(size_t)gm*ldc + gn] = v;
        }
    }
}

// -------------------- depthwise causal conv (k=4) + SiLU, float4 ------------
__global__ void dwconv_kernel(const float* __restrict__ xz,
                              const float* __restrict__ w,
                              const float* __restrict__ bias,
                              float* __restrict__ xc) {
    int gid = blockIdx.x * blockDim.x + threadIdx.x;   // over NTOK*DIN/4
    int d4 = gid % (DIN/4);
    int t  = (gid / (DIN/4)) % LSEQ;
    int b  = gid / ((DIN/4) * LSEQ);
    const float* xin = xz + (size_t)b * LSEQ * 2 * DIN + d4*4;
    float4 w0 = ((const float4*)w)[d4*4 + 0];
    float4 w1 = ((const float4*)w)[d4*4 + 1];
    float4 w2 = ((const float4*)w)[d4*4 + 2];
    float4 w3 = ((const float4*)w)[d4*4 + 3];
    float4 acc = ((const float4*)bias)[d4];
    #pragma unroll
    for (int k = 0; k < DCONV; k++) {
        int s = t - (DCONV-1) + k;
        if (s >= 0) {
            float4 xv = *(const float4*)(xin + (size_t)s*2*DIN);
            float wk0 = (&w0.x)[k], wk1 = (&w1.x)[k], wk2 = (&w2.x)[k], wk3 = (&w3.x)[k];
            acc.x += xv.x*wk0; acc.y += xv.y*wk1; acc.z += xv.z*wk2; acc.w += xv.w*wk3;
        }
    }
    acc.x = silu_fast(acc.x); acc.y = silu_fast(acc.y);
    acc.z = silu_fast(acc.z); acc.w = silu_fast(acc.w);
    ((float4*)xc)[gid] = acc;
}

// --------------- fused dt_proj + softplus + selective scan ------------------
// thread = (b, d); dbc/xc/z chunks double-buffered in smem via cp.async.
#define CH 32
#define NCH (LSEQ/CH)
#define DBC_OFF(bu) ((bu)*CH*64)
#define XC_OFF(bu)  (2*CH*64 + (bu)*CH*128)
#define ZZ_OFF(bu)  (2*CH*64 + 2*CH*128 + (bu)*CH*128)
#define SCAN_SMEM ((2*CH*64 + 4*CH*128)*4)
__global__ void __launch_bounds__(128) dtscan_kernel(
    const float* __restrict__ xc,
    const float* __restrict__ dbc,
    const float* __restrict__ dtw,   // (DIN, DTR)
    const float* __restrict__ dtb,   // (DIN)
    const float* __restrict__ A_log, // (DIN, NST)
    const float* __restrict__ Dp,    // (DIN)
    const float* __restrict__ xz,    // z at +DIN
    bf16* __restrict__ y) {
    extern __shared__ float smf[];
    const unsigned sbase = (unsigned)__cvta_generic_to_shared(smf);
    int b = blockIdx.x;
    int d0 = blockIdx.y * 128;
    int d = d0 + threadIdx.x;
    float h[NST], a[NST], w[DTR];
    #pragma unroll
    for (int n = 0; n < NST; n++) {
        h[n] = 0.f;
        a[n] = -__expf(A_log[d*NST + n]);
    }
    #pragma unroll
    for (int j = 0; j < DTR; j++) w[j] = dtw[d*DTR + j];
    float bias = dtb[d], Dd = Dp[d];
    bool geom = true;
    #pragma unroll
    for (int n = 1; n < NST; n++) {
        float pred = (float)(n+1) * a[0];
        if (fabsf(a[n] - pred) > 1e-4f * fmaxf(1.f, fabsf(a[n]))) geom = false;
    }
    const float* dbc_b = dbc + (size_t)b * LSEQ * 64;
    const float* xcb   = xc + (size_t)b * LSEQ * DIN + d0;
    const float* zzb   = xz + (size_t)b * LSEQ * 2 * DIN + DIN + d0;
    size_t ybase = (size_t)b * LSEQ * DIN + d;

    #define PRE(c_, bu_) do {                                                   \
        int t0_ = (c_)*CH;                                                      \
        for (int i_ = threadIdx.x; i_ < CH*16; i_ += 128) {                     \
            int tt_ = i_ >> 4, q_ = (i_ & 15) * 4;                              \
            CP_ASYNC16(sbase + (unsigned)((DBC_OFF(bu_) + tt_*64 + q_)*4),      \
                       dbc_b + (size_t)(t0_+tt_)*64 + q_);                      \
        }                                                                       \
        for (int i_ = threadIdx.x; i_ < CH*32; i_ += 128) {                     \
            int tt_ = i_ >> 5, q_ = (i_ & 31) * 4;                              \
            CP_ASYNC16(sbase + (unsigned)((XC_OFF(bu_) + tt_*128 + q_)*4),      \
                       xcb + (size_t)(t0_+tt_)*DIN + q_);                       \
            CP_ASYNC16(sbase + (unsigned)((ZZ_OFF(bu_) + tt_*128 + q_)*4),      \
                       zzb + (size_t)(t0_+tt_)*2*DIN + q_);                     \
        }                                                                       \
        asm volatile("cp.async.commit_group;");                                 \
    } while (0)

    PRE(0, 0);
    int bu = 0;
    for (int c = 0; c < NCH; c++) {
        asm volatile("cp.async.wait_group 0;");
        __syncthreads();
        if (c + 1 < NCH) PRE(c + 1, bu ^ 1);
        const float* dchunk = smf + DBC_OFF(bu);
        const float* xchunk = smf + XC_OFF(bu);
        const float* zchunk = smf + ZZ_OFF(bu);
        for (int tt = 0; tt < CH; tt++) {
            float u  = xchunk[tt*128 + threadIdx.x];
            float zv = zchunk[tt*128 + threadIdx.x];
            const float4* dr = (const float4*)(dchunk + tt*64);
            // dt_proj: 4 independent partial chains
            float v0 = bias, v1 = 0.f, v2 = 0.f, v3 = 0.f;
            #pragma unroll
            for (int j = 0; j < 2; j++) {
                float4 q0 = dr[4*j], q1 = dr[4*j+1], q2 = dr[4*j+2], q3 = dr[4*j+3];
                v0 += w[16*j+ 0]*q0.x + w[16*j+ 1]*q0.y + w[16*j+ 2]*q0.z + w[16*j+ 3]*q0.w;
                v1 += w[16*j+ 4]*q1.x + w[16*j+ 5]*q1.y + w[16*j+ 6]*q1.z + w[16*j+ 7]*q1.w;
                v2 += w[16*j+ 8]*q2.x + w[16*j+ 9]*q2.y + w[16*j+10]*q2.z + w[16*j+11]*q2.w;
                v3 += w[16*j+12]*q3.x + w[16*j+13]*q3.y + w[16*j+14]*q3.z + w[16*j+15]*q3.w;
            }
            float v = (v0 + v1) + (v2 + v3);
            float dt = (v > 20.f) ? v : __logf(1.f + __expf(v));
            float du = dt * u;
            const float4* Bv = (const float4*)(dchunk + tt*64 + DTR);
            const float4* Cv = (const float4*)(dchunk + tt*64 + DTR + NST);
            float dA[NST];
            if (geom) {
                float p1 = __expf(dt * a[0]);
                float p2 = p1*p1, p3 = p2*p1, p4 = p2*p2;
                float p5 = p4*p1, p6 = p4*p2, p7 = p4*p3, p8 = p4*p4;
                dA[0]=p1; dA[1]=p2; dA[2]=p3; dA[3]=p4;
                dA[4]=p5; dA[5]=p6; dA[6]=p7; dA[7]=p8;
                dA[8]=p8*p1; dA[9]=p8*p2; dA[10]=p8*p3; dA[11]=p8*p4;
                dA[12]=p8*p5; dA[13]=p8*p6; dA[14]=p8*p7; dA[15]=p8*p8;
            } else {
                #pragma unroll
                for (int n = 0; n < NST; n++) dA[n] = __expf(dt * a[n]);
            }
            float acc0 = 0.f, acc1 = 0.f;
            #pragma unroll
            for (int q = 0; q < 4; q++) {
                float4 Bq = Bv[q], Cq = Cv[q];
                h[4*q+0] = dA[4*q+0]*h[4*q+0] + du*Bq.x; acc0 += h[4*q+0]*Cq.x;
                h[4*q+1] = dA[4*q+1]*h[4*q+1] + du*Bq.y; acc1 += h[4*q+1]*Cq.y;
                h[4*q+2] = dA[4*q+2]*h[4*q+2] + du*Bq.z; acc0 += h[4*q+2]*Cq.z;
                h[4*q+3] = dA[4*q+3]*h[4*q+3] + du*Bq.w; acc1 += h[4*q+3]*Cq.w;
            }
            int t = c*CH + tt;
            y[ybase + (size_t)t*DIN] =
                __float2bfloat16(((acc0 + acc1) + u*Dd) * silu_fast(zv));
        }
        bu ^= 1;
    }
    #undef PRE
}

// --------------- output head: final LN + proj + denorm (fused) --------------
__global__ void outf_kernel(const float* __restrict__ x,
                            const float* __restrict__ fw,
                            const float* __restrict__ fb,
                            const float* __restrict__ out_w,
                            const float* __restrict__ mean,
                            const float* __restrict__ stdv,
                            float* __restrict__ out) {
    __shared__ float red[32];
    __shared__ float row[DM];
    int t_out = blockIdx.x, b = blockIdx.y;
    int r = b*LSEQ + LBL + t_out;
    int tid = threadIdx.x;             // 256
    const float* xr = x + (size_t)r*DM;
    float v0 = xr[tid], v1 = xr[tid + 256];
    float s = block_reduce_sum(v0 + v1, red);
    float m = s * (1.f/(float)DM);
    float d0 = v0 - m, d1 = v1 - m;
    float vs = block_reduce_sum(d0*d0 + d1*d1, red);
    float inv = rsqrtf(vs * (1.f/(float)DM) + EPSF);
    row[tid]       = d0*inv*fw[tid]       + fb[tid];
    row[tid + 256] = d1*inv*fw[tid + 256] + fb[tid + 256];
    __syncthreads();
    int c = tid >> 5, lane = tid & 31;
    if (c < CIN) {
        float acc = 0.f;
        #pragma unroll
        for (int i = 0; i < DM/32; i++) acc += row[lane + i*32] * out_w[c*DM + lane + i*32];
        #pragma unroll
        for (int o = 16; o; o >>= 1) acc += __shfl_xor_sync(0xffffffffu, acc, o);
        if (lane == 0)
            out[(size_t)(b*PRED + t_out)*CIN + c] = acc * stdv[b*CIN + c] + mean[b*CIN + c];
    }
}

// ------------------------------- launcher -----------------------------------
extern "C" void kernel_launch(void* const* d_in, const int* in_sizes, int n_in,
                              void* d_out, int out_size) {
    const float* x_dec    = (const float*)d_in[2];
    const float* mark     = (const float*)d_in[3];
    const float* token_w  = (const float*)d_in[4];
    const float* timef_w  = (const float*)d_in[5];
    const float* norm_w   = (const float*)d_in[6];
    const float* norm_b   = (const float*)d_in[7];
    const float* in_proj_w= (const float*)d_in[8];
    const float* conv_w   = (const float*)d_in[9];
    const float* conv_b   = (const float*)d_in[10];
    const float* xproj_w  = (const float*)d_in[11];
    const float* dtproj_w = (const float*)d_in[12];
    const float* dtproj_b = (const float*)d_in[13];
    const float* A_log    = (const float*)d_in[14];
    const float* Dp       = (const float*)d_in[15];
    const float* outproj_w= (const float*)d_in[16];
    const float* fin_w    = (const float*)d_in[17];
    const float* fin_b    = (const float*)d_in[18];
    const float* out_w    = (const float*)d_in[19];
    float* out = (float*)d_out;

    float *px, *pxz, *pxc, *pdbc, *pmean, *pstd, *pa28, *pw28;
    bf16 *pxnh, *pyh, *pwih, *pwoh;
    cudaGetSymbolAddress((void**)&px,   g_x);
    cudaGetSymbolAddress((void**)&pxnh, g_xnh);
    cudaGetSymbolAddress((void**)&pxz,  g_xz);
    cudaGetSymbolAddress((void**)&pxc,  g_xc);
    cudaGetSymbolAddress((void**)&pdbc, g_dbc);
    cudaGetSymbolAddress((void**)&pyh,  g_yh);
    cudaGetSymbolAddress((void**)&pmean,g_mean);
    cudaGetSymbolAddress((void**)&pstd, g_std);
    cudaGetSymbolAddress((void**)&pwih, g_wih);
    cudaGetSymbolAddress((void**)&pwoh, g_woh);
    cudaGetSymbolAddress((void**)&pa28, g_a28);
    cudaGetSymbolAddress((void**)&pw28, g_w28);

    const int SMEM_TC = 3*2*TILEH*2;   // 61440 bytes
    cudaFuncSetAttribute(gemm_bf<0>, cudaFuncAttributeMaxDynamicSharedMemorySize, SMEM_TC);
    cudaFuncSetAttribute(gemm_bf<2>, cudaFuncAttributeMaxDynamicSharedMemorySize, SMEM_TC);
    cudaFuncSetAttribute(dtscan_kernel, cudaFuncAttributeMaxDynamicSharedMemorySize, SCAN_SMEM);

    // one-time prep
    {
        int ni = NLAYER*2*DIN*DM, no = NLAYER*DM*DIN;
        cvtwh_kernel<<<(ni + 255)/256, 256>>>(in_proj_w, pwih, ni);
        cvtwh_kernel<<<(no + 255)/256, 256>>>(outproj_w, pwoh, no);
        w28_prep<<<(DM*KEMB + 255)/256, 256>>>(token_w, timef_w, pw28);
    }

    meanstd_kernel<<<BB*CIN, 32>>>(x_dec, pmean, pstd);
    embed_prep<<<(NTOK*KEMB + 255)/256, 256>>>(x_dec, mark, pmean, pstd, pa28);
    // embed GEMM: (6144x28) @ (512x28)^T -> (6144x512)
    gemm_kernel<64,64,28,4,4><<<dim3(DM/64, NTOK/64, 1), 256>>>(
        pa28, KEMB, pw28, nullptr, px, DM, NTOK, DM, KEMB, KEMB, 0);

    for (int l = 0; l < NLAYER; l++) {
        lnh_kernel<<<NTOK/8, 256>>>(px, norm_w + l*DM, norm_b + l*DM, pxnh);
        // in_proj: (6144x512) @ (2048x512)^T -> (6144x2048)
        gemm_bf<0><<<dim3(2*DIN/128, NTOK/128), 256, SMEM_TC>>>(
            pxnh, DM, pwih + (size_t)l*2*DIN*DM, pxz, 2*DIN, DM);
        dwconv_kernel<<<(NTOK*DIN/4)/256, 256>>>(pxz, conv_w + l*DIN*DCONV,
                                                 conv_b + l*DIN, pxc);
        // x_proj: (6144x1024) @ (64x1024)^T -> (6144x64), split-K x4
        cudaMemsetAsync(pdbc, 0, (size_t)NTOK*64*sizeof(float));
        gemm_kernel<64,64,16,4,4><<<dim3(1, NTOK/64, 4), 256>>>(
            pxc, DIN, xproj_w + (size_t)l*64*DIN, nullptr, pdbc, 64,
            NTOK, 64, DIN, DIN/4, 3);
        // fused dt_proj + softplus + selective scan + gate
        dtscan_kernel<<<dim3(BB, DIN/128), 128, SCAN_SMEM>>>(
            pxc, pdbc, dtproj_w + (size_t)l*DIN*DTR, dtproj_b + l*DIN,
            A_log + (size_t)l*DIN*NST, Dp + l*DIN, pxz, pyh);
        // out_proj (+residual): (6144x1024) @ (512x1024)^T -> += x
        gemm_bf<2><<<dim3(DM/128, NTOK/128), 256, SMEM_TC>>>(
            pyh, DIN, pwoh + (size_t)l*DM*DIN, px, DM, DIN);
    }

    outf_kernel<<<dim3(PRED, BB), 256>>>(px, fin_w, fin_b, out_w, pmean, pstd, out);
}

// round 15
// speedup vs baseline: 1.2680x; 1.0500x over previous
#include <cuda_runtime.h>
#include <cuda_bf16.h>
#include <stdint.h>
#include <math.h>

#define BB 16
#define LBL 48
#define PRED 336
#define LSEQ 384
#define CIN 7
#define TFD 4
#define DM 512
#define DIN 1024
#define NST 16
#define DTR 32
#define DCONV 4
#define NLAYER 2
#define EPSF 1e-5f

#define NTOK (BB*LSEQ)   // 6144 rows
#define KEMB 28

typedef __nv_bfloat16 bf16;

// ------------------- scratch (static device globals; no allocs) -------------
__device__ float g_x  [NTOK*DM];
__device__ bf16  g_xnh[NTOK*DM];
__device__ float g_xz [NTOK*2*DIN];
__device__ float g_xc [NTOK*DIN];
__device__ float g_dbc[NTOK*64];
__device__ bf16  g_yh [NTOK*DIN];
__device__ float g_mean[BB*CIN];
__device__ float g_std [BB*CIN];
__device__ bf16  g_wih[NLAYER*2*DIN*DM];
__device__ bf16  g_woh[NLAYER*DM*DIN];
__device__ float g_a28[NTOK*KEMB];
__device__ float g_w28[DM*KEMB];

// ------------------------------- helpers ------------------------------------
__device__ __forceinline__ float block_reduce_sum(float v, float* red) {
    __syncthreads();
    int lane = threadIdx.x & 31, wid = threadIdx.x >> 5;
    #pragma unroll
    for (int o = 16; o; o >>= 1) v += __shfl_xor_sync(0xffffffffu, v, o);
    if (lane == 0) red[wid] = v;
    __syncthreads();
    if (wid == 0) {
        float t = (lane < (int)(blockDim.x >> 5)) ? red[lane] : 0.f;
        #pragma unroll
        for (int o = 16; o; o >>= 1) t += __shfl_xor_sync(0xffffffffu, t, o);
        if (lane == 0) red[0] = t;
    }
    __syncthreads();
    return red[0];
}

__device__ __forceinline__ float silu_fast(float x) {
    return __fdividef(x, 1.f + __expf(-x));
}

#define CP_ASYNC16(dst, src) \
    asm volatile("cp.async.cg.shared.global [%0], [%1], 16;" :: "r"(dst), "l"(src))

__device__ __forceinline__ void ldsm_x4(unsigned& r0, unsigned& r1,
                                        unsigned& r2, unsigned& r3, unsigned addr) {
    asm volatile("ldmatrix.sync.aligned.m8n8.x4.shared.b16 {%0,%1,%2,%3}, [%4];"
                 : "=r"(r0), "=r"(r1), "=r"(r2), "=r"(r3) : "r"(addr));
}

// --------------------- weight bf16 pre-conversion ---------------------------
__global__ void cvtwh_kernel(const float* __restrict__ src, bf16* __restrict__ dst, int n) {
    int i = blockIdx.x * 256 + threadIdx.x;
    if (i < n) dst[i] = __float2bfloat16(src[i]);
}

// --------------------- mean/std over label window (warp per (b,c)) ----------
__global__ void meanstd_kernel(const float* __restrict__ x_dec,
                               float* __restrict__ mean, float* __restrict__ stdv) {
    int b = blockIdx.x / CIN, c = blockIdx.x % CIN;
    int lane = threadIdx.x;
    float s = 0.f;
    for (int t = lane; t < LBL; t += 32) s += x_dec[(b*LSEQ + t)*CIN + c];
    #pragma unroll
    for (int o = 16; o; o >>= 1) s += __shfl_xor_sync(0xffffffffu, s, o);
    float m = s / (float)LBL;
    float v = 0.f;
    for (int t = lane; t < LBL; t += 32) {
        float d = x_dec[(b*LSEQ + t)*CIN + c] - m;
        v += d*d;
    }
    #pragma unroll
    for (int o = 16; o; o >>= 1) v += __shfl_xor_sync(0xffffffffu, v, o);
    if (lane == 0) {
        mean[blockIdx.x] = m;
        stdv[blockIdx.x] = sqrtf(v / (float)LBL + EPSF);
    }
}

// ---------------- embed prep: window matrix + packed weights -----------------
__global__ void embed_prep(const float* __restrict__ x_dec,
                           const float* __restrict__ mark,
                           const float* __restrict__ mean,
                           const float* __restrict__ stdv,
                           float* __restrict__ A28) {
    int i = blockIdx.x * 256 + threadIdx.x;
    if (i >= NTOK*KEMB) return;
    int col = i % KEMB, tok = i / KEMB;
    int b = tok / LSEQ, t = tok % LSEQ;
    float v = 0.f;
    if (col < 21) {
        int c = col / 3, k = col % 3;
        int s = (t - 1 + k + LSEQ) % LSEQ;
        v = x_dec[(b*LSEQ + s)*CIN + c];
        if (s < LBL) v = (v - mean[b*CIN + c]) / stdv[b*CIN + c];
    } else if (col < 25) {
        v = mark[(b*LSEQ + t)*TFD + col - 21];
    }
    A28[i] = v;
}

__global__ void w28_prep(const float* __restrict__ token_w,
                         const float* __restrict__ timef_w,
                         float* __restrict__ W28) {
    int i = blockIdx.x * 256 + threadIdx.x;
    if (i >= DM*KEMB) return;
    int m = i / KEMB, j = i % KEMB;
    float v = 0.f;
    if (j < 21)      v = token_w[m*21 + j];
    else if (j < 25) v = timef_w[m*TFD + j - 21];
    W28[i] = v;
}

// -------------------- layernorm (warp per row of DM) -> bf16 ----------------
__global__ void lnh_kernel(const float* __restrict__ x,
                           const float* __restrict__ w,
                           const float* __restrict__ bb,
                           bf16* __restrict__ out) {
    int warp = threadIdx.x >> 5, lane = threadIdx.x & 31;
    int row = blockIdx.x * 8 + warp;
    const float4* xr = (const float4*)(x + (size_t)row*DM);
    float4 v[4];
    float s = 0.f;
    #pragma unroll
    for (int i = 0; i < 4; i++) {
        v[i] = xr[lane + i*32];
        s += (v[i].x + v[i].y) + (v[i].z + v[i].w);
    }
    #pragma unroll
    for (int o = 16; o; o >>= 1) s += __shfl_xor_sync(0xffffffffu, s, o);
    float m = s * (1.f/(float)DM);
    float vs = 0.f;
    #pragma unroll
    for (int i = 0; i < 4; i++) {
        v[i].x -= m; v[i].y -= m; v[i].z -= m; v[i].w -= m;
        vs += (v[i].x*v[i].x + v[i].y*v[i].y) + (v[i].z*v[i].z + v[i].w*v[i].w);
    }
    #pragma unroll
    for (int o = 16; o; o >>= 1) vs += __shfl_xor_sync(0xffffffffu, vs, o);
    float inv = rsqrtf(vs * (1.f/(float)DM) + EPSF);
    __nv_bfloat162* orow = (__nv_bfloat162*)(out + (size_t)row*DM);
    #pragma unroll
    for (int i = 0; i < 4; i++) {
        float4 wv = ((const float4*)w)[lane + i*32];
        float4 bv = ((const float4*)bb)[lane + i*32];
        float o0 = v[i].x*inv*wv.x + bv.x;
        float o1 = v[i].y*inv*wv.y + bv.y;
        float o2 = v[i].z*inv*wv.z + bv.z;
        float o3 = v[i].w*inv*wv.w + bv.w;
        orow[(lane + i*32)*2]     = __floats2bfloat162_rn(o0, o1);
        orow[(lane + i*32)*2 + 1] = __floats2bfloat162_rn(o2, o3);
    }
}

// ---------------------- BF16 tensor-core GEMM, cp.async 3-stage --------------
// ldmatrix fragment loads. MODE 0: store. MODE 2: C += (residual).
#define SROWH 40
#define TILEH (128*SROWH)   // halves
template<int MODE>
__global__ void __launch_bounds__(256, 2) gemm_bf(const bf16* __restrict__ A, int lda,
                                                  const bf16* __restrict__ W,
                                                  float* __restrict__ C, int ldc,
                                                  int K) {
    extern __shared__ bf16 smh[];
    const int tid = threadIdx.x;
    const int lane = tid & 31, warp = tid >> 5;
    const int wm = warp >> 1, wn = warp & 1;
    const int row0 = blockIdx.y * 128, col0 = blockIdx.x * 128;
    const int KT = K >> 5;
    const unsigned sbase = (unsigned)__cvta_generic_to_shared(smh);

    // ldmatrix per-lane offsets (in halves, within one stage)
    const int lr = lane & 7, lg = lane >> 3;
    unsigned offA[2], offB[4];
    #pragma unroll
    for (int i = 0; i < 2; i++)
        offA[i] = (unsigned)((wm*32 + i*16 + lr + (lg & 1)*8) * SROWH + (lg >> 1)*8);
    #pragma unroll
    for (int p = 0; p < 4; p++)
        offB[p] = (unsigned)(TILEH + (wn*64 + p*16 + lr + (lg >> 1)*8) * SROWH + (lg & 1)*8);

    float acc[2][8][4];
    #pragma unroll
    for (int i = 0; i < 2; i++)
        #pragma unroll
        for (int j = 0; j < 8; j++)
            #pragma unroll
            for (int q = 0; q < 4; q++) acc[i][j][q] = 0.f;

    #define ISSUE(kt_, s_) do {                                                 \
        int k0_ = (kt_) << 5;                                                   \
        _Pragma("unroll")                                                       \
        for (int h_ = 0; h_ < 2; h_++) {                                        \
            int c_ = tid + h_*256;                                              \
            int r_ = c_ >> 2, q_ = (c_ & 3) * 8;                                \
            const bf16* ga_ = A + (size_t)(row0 + r_)*lda + k0_ + q_;           \
            const bf16* gb_ = W + (size_t)(col0 + r_)*K   + k0_ + q_;           \
            unsigned da_ = sbase + (unsigned)(((s_)*2*TILEH + r_*SROWH + q_)*2);\
            unsigned db_ = sbase + (unsigned)(((s_)*2*TILEH + TILEH + r_*SROWH + q_)*2); \
            CP_ASYNC16(da_, ga_);                                               \
            CP_ASYNC16(db_, gb_);                                               \
        }                                                                       \
        asm volatile("cp.async.commit_group;");                                 \
    } while (0)

    ISSUE(0, 0);
    ISSUE(1, 1);

    for (int kt = 0; kt < KT; kt++) {
        if (kt + 2 < KT) asm volatile("cp.async.wait_group 1;");
        else             asm volatile("cp.async.wait_group 0;");
        __syncthreads();
        if (kt + 2 < KT) ISSUE(kt + 2, (kt + 2) % 3);

        const unsigned stoff = sbase + (unsigned)(((kt % 3) * 2 * TILEH) * 2);

        #pragma unroll
        for (int kk = 0; kk < 2; kk++) {
            const unsigned kadd = (unsigned)(kk * 16 * 2);   // bytes
            unsigned a0[2], a1[2], a2[2], a3[2];
            #pragma unroll
            for (int i = 0; i < 2; i++)
                ldsm_x4(a0[i], a1[i], a2[i], a3[i], stoff + offA[i]*2 + kadd);
            #pragma unroll
            for (int p = 0; p < 4; p++) {
                unsigned b0a, b1a, b0b, b1b;
                ldsm_x4(b0a, b1a, b0b, b1b, stoff + offB[p]*2 + kadd);
                #pragma unroll
                for (int i = 0; i < 2; i++) {
                    asm volatile(
                        "mma.sync.aligned.m16n8k16.row.col.f32.bf16.bf16.f32 "
                        "{%0,%1,%2,%3}, {%4,%5,%6,%7}, {%8,%9}, {%0,%1,%2,%3};"
                        : "+f"(acc[i][2*p][0]), "+f"(acc[i][2*p][1]),
                          "+f"(acc[i][2*p][2]), "+f"(acc[i][2*p][3])
                        : "r"(a0[i]), "r"(a1[i]), "r"(a2[i]), "r"(a3[i]),
                          "r"(b0a), "r"(b1a));
                    asm volatile(
                        "mma.sync.aligned.m16n8k16.row.col.f32.bf16.bf16.f32 "
                        "{%0,%1,%2,%3}, {%4,%5,%6,%7}, {%8,%9}, {%0,%1,%2,%3};"
                        : "+f"(acc[i][2*p+1][0]), "+f"(acc[i][2*p+1][1]),
                          "+f"(acc[i][2*p+1][2]), "+f"(acc[i][2*p+1][3])
                        : "r"(a0[i]), "r"(a1[i]), "r"(a2[i]), "r"(a3[i]),
                          "r"(b0b), "r"(b1b));
                }
            }
        }
    }
    #undef ISSUE

    #pragma unroll
    for (int i = 0; i < 2; i++) {
        int gr = row0 + wm*32 + i*16 + (lane >> 2);
        #pragma unroll
        for (int j = 0; j < 8; j++) {
            int gc = col0 + wn*64 + j*8 + (lane & 3)*2;
            float* p0 = C + (size_t)gr*ldc + gc;
            float* p1 = C + (size_t)(gr + 8)*ldc + gc;
            if (MODE == 2) {
                p0[0] += acc[i][j][0]; p0[1] += acc[i][j][1];
                p1[0] += acc[i][j][2]; p1[1] += acc[i][j][3];
            } else {
                p0[0] = acc[i][j][0]; p0[1] = acc[i][j][1];
                p1[0] = acc[i][j][2]; p1[1] = acc[i][j][3];
            }
        }
    }
}

// ------------------------------ SIMT GEMM ------------------------------------
// mode 0: store.  mode 3: atomicAdd (split-K).
template<int BM, int BN, int BK, int TM, int TN>
__global__ void gemm_kernel(const float* __restrict__ A, int lda,
                            const float* __restrict__ W,
                            const float* __restrict__ bias,
                            float* __restrict__ C, int ldc,
                            int M, int Nn, int K, int KC, int mode) {
    constexpr int THREADS = (BM/TM)*(BN/TN);
    __shared__ float As[BK][BM];
    __shared__ float Bs[BK][BN];
    int tid = threadIdx.x;
    int tx = tid % (BN/TN);
    int ty = tid / (BN/TN);
    int row0 = blockIdx.y * BM;
    int col0 = blockIdx.x * BN;
    int kbeg = blockIdx.z * KC;
    float acc[TM][TN];
    #pragma unroll
    for (int i = 0; i < TM; i++)
        #pragma unroll
        for (int j = 0; j < TN; j++) acc[i][j] = 0.f;

    for (int k0 = kbeg; k0 < kbeg + KC; k0 += BK) {
        #pragma unroll
        for (int i = tid; i < BM*BK; i += THREADS) {
            int m = i / BK, kk = i % BK;
            As[kk][m] = A[(size_t)(row0 + m)*lda + k0 + kk];
        }
        #pragma unroll
        for (int i = tid; i < BN*BK; i += THREADS) {
            int n = i / BK, kk = i % BK;
            Bs[kk][n] = W[(size_t)(col0 + n)*K + k0 + kk];
        }
        __syncthreads();
        #pragma unroll
        for (int kk = 0; kk < BK; kk++) {
            float a[TM], bfr[TN];
            #pragma unroll
            for (int i = 0; i < TM; i++) a[i] = As[kk][ty*TM + i];
            #pragma unroll
            for (int j = 0; j < TN; j++) bfr[j] = Bs[kk][tx*TN + j];
            #pragma unroll
            for (int i = 0; i < TM; i++)
                #pragma unroll
                for (int j = 0; j < TN; j++) acc[i][j] += a[i]*bfr[j];
        }
        __syncthreads();
    }
    #pragma unroll
    for (int i = 0; i < TM; i++) {
        int gm = row0 + ty*TM + i;
        #pragma unroll
        for (int j = 0; j < TN; j++) {
            int gn = col0 + tx*TN + j;
            float v = acc[i][j];
            if (mode == 3)      atomicAdd(&C[(size_t)gm*ldc + gn], v);
            else                C[(size_t)gm*ldc + gn] = v;
        }
    }
}

// -------------------- depthwise causal conv (k=4) + SiLU, float4 ------------
__global__ void dwconv_kernel(const float* __restrict__ xz,
                              const float* __restrict__ w,
                              const float* __restrict__ bias,
                              float* __restrict__ xc) {
    int gid = blockIdx.x * blockDim.x + threadIdx.x;   // over NTOK*DIN/4
    int d4 = gid % (DIN/4);
    int t  = (gid / (DIN/4)) % LSEQ;
    int b  = gid / ((DIN/4) * LSEQ);
    const float* xin = xz + (size_t)b * LSEQ * 2 * DIN + d4*4;
    float4 w0 = ((const float4*)w)[d4*4 + 0];
    float4 w1 = ((const float4*)w)[d4*4 + 1];
    float4 w2 = ((const float4*)w)[d4*4 + 2];
    float4 w3 = ((const float4*)w)[d4*4 + 3];
    float4 acc = ((const float4*)bias)[d4];
    #pragma unroll
    for (int k = 0; k < DCONV; k++) {
        int s = t - (DCONV-1) + k;
        if (s >= 0) {
            float4 xv = *(const float4*)(xin + (size_t)s*2*DIN);
            float wk0 = (&w0.x)[k], wk1 = (&w1.x)[k], wk2 = (&w2.x)[k], wk3 = (&w3.x)[k];
            acc.x += xv.x*wk0; acc.y += xv.y*wk1; acc.z += xv.z*wk2; acc.w += xv.w*wk3;
        }
    }
    acc.x = silu_fast(acc.x); acc.y = silu_fast(acc.y);
    acc.z = silu_fast(acc.z); acc.w = silu_fast(acc.w);
    ((float4*)xc)[gid] = acc;
}

// --------------- fused dt_proj + softplus + selective scan ------------------
// thread = (b, d); dbc/xc/z chunks double-buffered in smem via cp.async.
#define CH 32
#define NCH (LSEQ/CH)
#define DBC_OFF(bu) ((bu)*CH*64)
#define XC_OFF(bu)  (2*CH*64 + (bu)*CH*128)
#define ZZ_OFF(bu)  (2*CH*64 + 2*CH*128 + (bu)*CH*128)
#define SCAN_SMEM ((2*CH*64 + 4*CH*128)*4)
__global__ void __launch_bounds__(128) dtscan_kernel(
    const float* __restrict__ xc,
    const float* __restrict__ dbc,
    const float* __restrict__ dtw,   // (DIN, DTR)
    const float* __restrict__ dtb,   // (DIN)
    const float* __restrict__ A_log, // (DIN, NST)
    const float* __restrict__ Dp,    // (DIN)
    const float* __restrict__ xz,    // z at +DIN
    bf16* __restrict__ y) {
    extern __shared__ float smf[];
    const unsigned sbase = (unsigned)__cvta_generic_to_shared(smf);
    int b = blockIdx.x;
    int d0 = blockIdx.y * 128;
    int d = d0 + threadIdx.x;
    float h[NST], a[NST], w[DTR];
    #pragma unroll
    for (int n = 0; n < NST; n++) {
        h[n] = 0.f;
        a[n] = -__expf(A_log[d*NST + n]);
    }
    #pragma unroll
    for (int j = 0; j < DTR; j++) w[j] = dtw[d*DTR + j];
    float bias = dtb[d], Dd = Dp[d];
    bool geom = true;
    #pragma unroll
    for (int n = 1; n < NST; n++) {
        float pred = (float)(n+1) * a[0];
        if (fabsf(a[n] - pred) > 1e-4f * fmaxf(1.f, fabsf(a[n]))) geom = false;
    }
    const float* dbc_b = dbc + (size_t)b * LSEQ * 64;
    const float* xcb   = xc + (size_t)b * LSEQ * DIN + d0;
    const float* zzb   = xz + (size_t)b * LSEQ * 2 * DIN + DIN + d0;
    size_t ybase = (size_t)b * LSEQ * DIN + d;

    #define PRE(c_, bu_) do {                                                   \
        int t0_ = (c_)*CH;                                                      \
        for (int i_ = threadIdx.x; i_ < CH*16; i_ += 128) {                     \
            int tt_ = i_ >> 4, q_ = (i_ & 15) * 4;                              \
            CP_ASYNC16(sbase + (unsigned)((DBC_OFF(bu_) + tt_*64 + q_)*4),      \
                       dbc_b + (size_t)(t0_+tt_)*64 + q_);                      \
        }                                                                       \
        for (int i_ = threadIdx.x; i_ < CH*32; i_ += 128) {                     \
            int tt_ = i_ >> 5, q_ = (i_ & 31) * 4;                              \
            CP_ASYNC16(sbase + (unsigned)((XC_OFF(bu_) + tt_*128 + q_)*4),      \
                       xcb + (size_t)(t0_+tt_)*DIN + q_);                       \
            CP_ASYNC16(sbase + (unsigned)((ZZ_OFF(bu_) + tt_*128 + q_)*4),      \
                       zzb + (size_t)(t0_+tt_)*2*DIN + q_);                     \
        }                                                                       \
        asm volatile("cp.async.commit_group;");                                 \
    } while (0)

    PRE(0, 0);
    int bu = 0;
    for (int c = 0; c < NCH; c++) {
        asm volatile("cp.async.wait_group 0;");
        __syncthreads();
        if (c + 1 < NCH) PRE(c + 1, bu ^ 1);
        const float* dchunk = smf + DBC_OFF(bu);
        const float* xchunk = smf + XC_OFF(bu);
        const float* zchunk = smf + ZZ_OFF(bu);
        for (int tt = 0; tt < CH; tt++) {
            float u  = xchunk[tt*128 + threadIdx.x];
            float zv = zchunk[tt*128 + threadIdx.x];
            const float4* dr = (const float4*)(dchunk + tt*64);
            // dt_proj: 4 independent partial chains
            float v0 = bias, v1 = 0.f, v2 = 0.f, v3 = 0.f;
            #pragma unroll
            for (int j = 0; j < 2; j++) {
                float4 q0 = dr[4*j], q1 = dr[4*j+1], q2 = dr[4*j+2], q3 = dr[4*j+3];
                v0 += w[16*j+ 0]*q0.x + w[16*j+ 1]*q0.y + w[16*j+ 2]*q0.z + w[16*j+ 3]*q0.w;
                v1 += w[16*j+ 4]*q1.x + w[16*j+ 5]*q1.y + w[16*j+ 6]*q1.z + w[16*j+ 7]*q1.w;
                v2 += w[16*j+ 8]*q2.x + w[16*j+ 9]*q2.y + w[16*j+10]*q2.z + w[16*j+11]*q2.w;
                v3 += w[16*j+12]*q3.x + w[16*j+13]*q3.y + w[16*j+14]*q3.z + w[16*j+15]*q3.w;
            }
            float v = (v0 + v1) + (v2 + v3);
            float dt = (v > 20.f) ? v : __logf(1.f + __expf(v));
            float du = dt * u;
            const float4* Bv = (const float4*)(dchunk + tt*64 + DTR);
            const float4* Cv = (const float4*)(dchunk + tt*64 + DTR + NST);
            float dA[NST];
            if (geom) {
                float p1 = __expf(dt * a[0]);
                float p2 = p1*p1, p3 = p2*p1, p4 = p2*p2;
                float p5 = p4*p1, p6 = p4*p2, p7 = p4*p3, p8 = p4*p4;
                dA[0]=p1; dA[1]=p2; dA[2]=p3; dA[3]=p4;
                dA[4]=p5; dA[5]=p6; dA[6]=p7; dA[7]=p8;
                dA[8]=p8*p1; dA[9]=p8*p2; dA[10]=p8*p3; dA[11]=p8*p4;
                dA[12]=p8*p5; dA[13]=p8*p6; dA[14]=p8*p7; dA[15]=p8*p8;
            } else {
                #pragma unroll
                for (int n = 0; n < NST; n++) dA[n] = __expf(dt * a[n]);
            }
            float acc0 = 0.f, acc1 = 0.f;
            #pragma unroll
            for (int q = 0; q < 4; q++) {
                float4 Bq = Bv[q], Cq = Cv[q];
                h[4*q+0] = dA[4*q+0]*h[4*q+0] + du*Bq.x; acc0 += h[4*q+0]*Cq.x;
                h[4*q+1] = dA[4*q+1]*h[4*q+1] + du*Bq.y; acc1 += h[4*q+1]*Cq.y;
                h[4*q+2] = dA[4*q+2]*h[4*q+2] + du*Bq.z; acc0 += h[4*q+2]*Cq.z;
                h[4*q+3] = dA[4*q+3]*h[4*q+3] + du*Bq.w; acc1 += h[4*q+3]*Cq.w;
            }
            int t = c*CH + tt;
            y[ybase + (size_t)t*DIN] =
                __float2bfloat16(((acc0 + acc1) + u*Dd) * silu_fast(zv));
        }
        bu ^= 1;
    }
    #undef PRE
}

// --------------- output head: final LN + proj + denorm (fused) --------------
__global__ void outf_kernel(const float* __restrict__ x,
                            const float* __restrict__ fw,
                            const float* __restrict__ fb,
                            const float* __restrict__ out_w,
                            const float* __restrict__ mean,
                            const float* __restrict__ stdv,
                            float* __restrict__ out) {
    __shared__ float red[32];
    __shared__ float row[DM];
    int t_out = blockIdx.x, b = blockIdx.y;
    int r = b*LSEQ + LBL + t_out;
    int tid = threadIdx.x;             // 256
    const float* xr = x + (size_t)r*DM;
    float v0 = xr[tid], v1 = xr[tid + 256];
    float s = block_reduce_sum(v0 + v1, red);
    float m = s * (1.f/(float)DM);
    float d0 = v0 - m, d1 = v1 - m;
    float vs = block_reduce_sum(d0*d0 + d1*d1, red);
    float inv = rsqrtf(vs * (1.f/(float)DM) + EPSF);
    row[tid]       = d0*inv*fw[tid]       + fb[tid];
    row[tid + 256] = d1*inv*fw[tid + 256] + fb[tid + 256];
    __syncthreads();
    int c = tid >> 5, lane = tid & 31;
    if (c < CIN) {
        float acc = 0.f;
        #pragma unroll
        for (int i = 0; i < DM/32; i++) acc += row[lane + i*32] * out_w[c*DM + lane + i*32];
        #pragma unroll
        for (int o = 16; o; o >>= 1) acc += __shfl_xor_sync(0xffffffffu, acc, o);
        if (lane == 0)
            out[(size_t)(b*PRED + t_out)*CIN + c] = acc * stdv[b*CIN + c] + mean[b*CIN + c];
    }
}

// ------------------------------- launcher -----------------------------------
extern "C" void kernel_launch(void* const* d_in, const int* in_sizes, int n_in,
                              void* d_out, int out_size) {
    const float* x_dec    = (const float*)d_in[2];
    const float* mark     = (const float*)d_in[3];
    const float* token_w  = (const float*)d_in[4];
    const float* timef_w  = (const float*)d_in[5];
    const float* norm_w   = (const float*)d_in[6];
    const float* norm_b   = (const float*)d_in[7];
    const float* in_proj_w= (const float*)d_in[8];
    const float* conv_w   = (const float*)d_in[9];
    const float* conv_b   = (const float*)d_in[10];
    const float* xproj_w  = (const float*)d_in[11];
    const float* dtproj_w = (const float*)d_in[12];
    const float* dtproj_b = (const float*)d_in[13];
    const float* A_log    = (const float*)d_in[14];
    const float* Dp       = (const float*)d_in[15];
    const float* outproj_w= (const float*)d_in[16];
    const float* fin_w    = (const float*)d_in[17];
    const float* fin_b    = (const float*)d_in[18];
    const float* out_w    = (const float*)d_in[19];
    float* out = (float*)d_out;

    float *px, *pxz, *pxc, *pdbc, *pmean, *pstd, *pa28, *pw28;
    bf16 *pxnh, *pyh, *pwih, *pwoh;
    cudaGetSymbolAddress((void**)&px,   g_x);
    cudaGetSymbolAddress((void**)&pxnh, g_xnh);
    cudaGetSymbolAddress((void**)&pxz,  g_xz);
    cudaGetSymbolAddress((void**)&pxc,  g_xc);
    cudaGetSymbolAddress((void**)&pdbc, g_dbc);
    cudaGetSymbolAddress((void**)&pyh,  g_yh);
    cudaGetSymbolAddress((void**)&pmean,g_mean);
    cudaGetSymbolAddress((void**)&pstd, g_std);
    cudaGetSymbolAddress((void**)&pwih, g_wih);
    cudaGetSymbolAddress((void**)&pwoh, g_woh);
    cudaGetSymbolAddress((void**)&pa28, g_a28);
    cudaGetSymbolAddress((void**)&pw28, g_w28);

    const int SMEM_TC = 3*2*TILEH*2;   // 61440 bytes
    cudaFuncSetAttribute(gemm_bf<0>, cudaFuncAttributeMaxDynamicSharedMemorySize, SMEM_TC);
    cudaFuncSetAttribute(gemm_bf<2>, cudaFuncAttributeMaxDynamicSharedMemorySize, SMEM_TC);
    cudaFuncSetAttribute(dtscan_kernel, cudaFuncAttributeMaxDynamicSharedMemorySize, SCAN_SMEM);

    // one-time prep
    {
        int ni = NLAYER*2*DIN*DM, no = NLAYER*DM*DIN;
        cvtwh_kernel<<<(ni + 255)/256, 256>>>(in_proj_w, pwih, ni);
        cvtwh_kernel<<<(no + 255)/256, 256>>>(outproj_w, pwoh, no);
        w28_prep<<<(DM*KEMB + 255)/256, 256>>>(token_w, timef_w, pw28);
    }

    meanstd_kernel<<<BB*CIN, 32>>>(x_dec, pmean, pstd);
    embed_prep<<<(NTOK*KEMB + 255)/256, 256>>>(x_dec, mark, pmean, pstd, pa28);
    // embed GEMM: (6144x28) @ (512x28)^T -> (6144x512)
    gemm_kernel<64,64,28,4,4><<<dim3(DM/64, NTOK/64, 1), 256>>>(
        pa28, KEMB, pw28, nullptr, px, DM, NTOK, DM, KEMB, KEMB, 0);

    for (int l = 0; l < NLAYER; l++) {
        lnh_kernel<<<NTOK/8, 256>>>(px, norm_w + l*DM, norm_b + l*DM, pxnh);
        // in_proj: (6144x512) @ (2048x512)^T -> (6144x2048)
        gemm_bf<0><<<dim3(2*DIN/128, NTOK/128), 256, SMEM_TC>>>(
            pxnh, DM, pwih + (size_t)l*2*DIN*DM, pxz, 2*DIN, DM);
        dwconv_kernel<<<(NTOK*DIN/4)/256, 256>>>(pxz, conv_w + l*DIN*DCONV,
                                                 conv_b + l*DIN, pxc);
        // x_proj: (6144x1024) @ (64x1024)^T -> (6144x64), split-K x4
        cudaMemsetAsync(pdbc, 0, (size_t)NTOK*64*sizeof(float));
        gemm_kernel<64,64,16,4,4><<<dim3(1, NTOK/64, 4), 256>>>(
            pxc, DIN, xproj_w + (size_t)l*64*DIN, nullptr, pdbc, 64,
            NTOK, 64, DIN, DIN/4, 3);
        // fused dt_proj + softplus + selective scan + gate
        dtscan_kernel<<<dim3(BB, DIN/128), 128, SCAN_SMEM>>>(
            pxc, pdbc, dtproj_w + (size_t)l*DIN*DTR, dtproj_b + l*DIN,
            A_log + (size_t)l*DIN*NST, Dp + l*DIN, pxz, pyh);
        // out_proj (+residual): (6144x1024) @ (512x1024)^T -> += x
        gemm_bf<2><<<dim3(DM/128, NTOK/128), 256, SMEM_TC>>>(
            pyh, DIN, pwoh + (size_t)l*DM*DIN, px, DM, DIN);
    }

    outf_kernel<<<dim3(PRED, BB), 256>>>(px, fin_w, fin_b, out_w, pmean, pstd, out);
}